// round 12
// baseline (speedup 1.0000x reference)
#include <cuda_runtime.h>
#include <cuda_bf16.h>

// Problem constants (fixed by setup_inputs): d=64, nq=1024, nk=2048, batch=1
#define D   64
#define NQ  1024
#define NK  2048

typedef unsigned long long ull;

// Scratch: projected features stored TRANSPOSED (h-major)
__device__ float g_qpbT[D * NQ];   // qpbT[h][q] = b1[h] + sum_d W1q[h][d] query[d][q]
__device__ float g_kpbT[D * NK];   // kpbT[h][k] =         sum_d W1k[h][d] key[d][k]
__device__ float g_tilemax[NQ * 16];  // per (q, k-tile of 128) score max

// ---- packed f32x2 helpers -------------------------------------------------
__device__ __forceinline__ void fma2(ull& acc, ull a, ull b) {
    asm("fma.rn.f32x2 %0, %1, %2, %0;" : "+l"(acc) : "l"(a), "l"(b));
}
__device__ __forceinline__ void relu_wfma2(ull& acc, ull q2, ull k2, ull w2) {
    asm("{\n\t"
        ".reg .b64 t;\n\t"
        ".reg .f32 lo, hi;\n\t"
        "add.rn.f32x2 t, %1, %2;\n\t"
        "mov.b64 {lo, hi}, t;\n\t"
        "max.f32 lo, lo, 0f00000000;\n\t"
        "max.f32 hi, hi, 0f00000000;\n\t"
        "mov.b64 t, {lo, hi};\n\t"
        "fma.rn.f32x2 %0, %3, t, %0;\n\t"
        "}" : "+l"(acc) : "l"(q2), "l"(k2), "l"(w2));
}
__device__ __forceinline__ float2 upk(ull v) {
    float2 f;
    asm("mov.b64 {%0, %1}, %2;" : "=f"(f.x), "=f"(f.y) : "l"(v));
    return f;
}
__device__ __forceinline__ ull pk(float a, float b) {
    ull r;
    asm("mov.b64 %0, {%1, %2};" : "=l"(r) : "f"(a), "f"(b));
    return r;
}

// ---------------------------------------------------------------------------
// K1: projection GEMMs. Block = 32 cols x 16 h, grid (96, 4).
// x staged TRANSPOSED [c][d] (stride 68: 16B aligned, conflict-free), w [h][d].
// Compute loop: per 4 d -> 3x LDS.128 + 8 FMA, fully hoistable.
// ---------------------------------------------------------------------------
__global__ __launch_bounds__(256)
void k1_project(const float* __restrict__ query,
                const float* __restrict__ key,
                const float* __restrict__ W1,
                const float* __restrict__ b1)
{
    __shared__ float x_s[32 * 68];   // [c][d]
    __shared__ float w_s[16 * 68];   // [hl][d]

    int tid     = threadIdx.x;
    int colbase = blockIdx.x * 32;
    int hbase   = blockIdx.y * 16;
    bool isQ    = (colbase < NQ);
    int off     = isQ ? 0 : 64;
    int stride  = isQ ? NQ : NK;
    int cb      = isQ ? colbase : colbase - NQ;
    const float* src = isQ ? query : key;

    // x tile 64d x 32c: read float4 along c, scatter-transpose into [c][d]
    #pragma unroll
    for (int it = 0; it < 2; it++) {
        int i = tid + it * 256;              // 512 float4s
        int d = i >> 3, c4 = (i & 7) << 2;
        float4 v = *(const float4*)&src[d * stride + cb + c4];
        x_s[(c4 + 0) * 68 + d] = v.x;
        x_s[(c4 + 1) * 68 + d] = v.y;
        x_s[(c4 + 2) * 68 + d] = v.z;
        x_s[(c4 + 3) * 68 + d] = v.w;
    }
    // w tile 16h x 64d, row-major
    #pragma unroll
    for (int it = 0; it < 4; it++) {
        int i = tid + it * 256;
        int d = i & 63, hl = i >> 6;
        w_s[hl * 68 + d] = W1[(hbase + hl) * 128 + off + d];
    }
    __syncthreads();

    int lane = tid & 31;
    int hl0  = (tid >> 5) * 2;

    float acc0 = isQ ? b1[hbase + hl0]     : 0.0f;
    float acc1 = isQ ? b1[hbase + hl0 + 1] : 0.0f;

    #pragma unroll
    for (int d4 = 0; d4 < 64; d4 += 4) {
        float4 x  = *(const float4*)&x_s[lane * 68 + d4];
        float4 w0 = *(const float4*)&w_s[hl0 * 68 + d4];
        float4 w1 = *(const float4*)&w_s[(hl0 + 1) * 68 + d4];
        acc0 = fmaf(w0.x, x.x, acc0); acc1 = fmaf(w1.x, x.x, acc1);
        acc0 = fmaf(w0.y, x.y, acc0); acc1 = fmaf(w1.y, x.y, acc1);
        acc0 = fmaf(w0.z, x.z, acc0); acc1 = fmaf(w1.z, x.z, acc1);
        acc0 = fmaf(w0.w, x.w, acc0); acc1 = fmaf(w1.w, x.w, acc1);
    }

    float* dst = isQ ? g_qpbT : g_kpbT;
    dst[(hbase + hl0)     * stride + cb + lane] = acc0;
    dst[(hbase + hl0 + 1) * stride + cb + lane] = acc1;
}

// ---------------------------------------------------------------------------
// K2: scores[q][k] = b2 + sum_h W2[h] * relu(qpb[q][h] + kpb[k][h])
// Tile 64q x 128k per block, 256 threads, per-thread 4q x 8k, packed f32x2.
// Accumulators init with packed bias. Also writes per-(row, k-tile) maxima
// to g_tilemax (k3 derives rowmax from these: no full stats pass needed).
// Grid (NK/128, NQ/64) = (16, 16).
// ---------------------------------------------------------------------------
__global__ __launch_bounds__(256)
void k2_scores(const float* __restrict__ W2,
               const float* __restrict__ b2,
               float* __restrict__ scores)
{
    __shared__ float qs2[64 * 132];   // [h][2*64]  duplicated q values
    __shared__ float ks [64 * 132];   // [h][128]
    __shared__ float w2d[128];        // duplicated W2

    int tid   = threadIdx.x;
    int qbase = blockIdx.y * 64;
    int kbase = blockIdx.x * 128;

    #pragma unroll
    for (int it = 0; it < 16; it++) {
        int i = tid + it * 256;               // 64h x 64r
        int h = i >> 6, r = i & 63;
        float v = g_qpbT[h * NQ + qbase + r];
        *(float2*)&qs2[h * 132 + 2 * r] = make_float2(v, v);
    }
    #pragma unroll
    for (int it = 0; it < 8; it++) {
        int i = tid + it * 256;               // 64h x 32 float4
        int h = i >> 5, c4 = (i & 31) << 2;
        *(float4*)&ks[h * 132 + c4] = *(const float4*)&g_kpbT[h * NK + kbase + c4];
    }
    if (tid < 64) {
        float w = W2[tid];
        *(float2*)&w2d[2 * tid] = make_float2(w, w);
    }
    __syncthreads();

    int qg = tid >> 4;        // 0..15 -> q rows 4qg..4qg+3
    int kg = tid & 15;        // 0..15 -> k cols {4kg..} u {64+4kg..}

    float bias = b2[0];
    ull bini = pk(bias, bias);
    ull acc[4][4];
    #pragma unroll
    for (int i = 0; i < 4; i++)
        #pragma unroll
        for (int j = 0; j < 4; j++) acc[i][j] = bini;

    #pragma unroll 4
    for (int h = 0; h < 64; h++) {
        ull w2v = *(const ull*)&w2d[2 * h];
        const float* qrow = &qs2[h * 132 + 8 * qg];
        ulonglong2 qA = *(const ulonglong2*)qrow;
        ulonglong2 qB = *(const ulonglong2*)(qrow + 4);
        ulonglong2 kA = *(const ulonglong2*)&ks[h * 132 + 4 * kg];
        ulonglong2 kB = *(const ulonglong2*)&ks[h * 132 + 64 + 4 * kg];
        ull qd[4] = {qA.x, qA.y, qB.x, qB.y};
        ull kp[4] = {kA.x, kA.y, kB.x, kB.y};
        #pragma unroll
        for (int i = 0; i < 4; i++)
            #pragma unroll
            for (int j = 0; j < 4; j++)
                relu_wfma2(acc[i][j], qd[i], kp[j], w2v);
    }

    #pragma unroll
    for (int i = 0; i < 4; i++) {
        float* row = &scores[(qbase + 4 * qg + i) * NK + kbase];
        float2 a0 = upk(acc[i][0]), a1 = upk(acc[i][1]);
        float2 a2 = upk(acc[i][2]), a3 = upk(acc[i][3]);
        *(float4*)&row[4 * kg]      = make_float4(a0.x, a0.y, a1.x, a1.y);
        *(float4*)&row[64 + 4 * kg] = make_float4(a2.x, a2.y, a3.x, a3.y);

        // per-row max over this thread's 8 k, then over the 16 kg owners
        float m = fmaxf(fmaxf(fmaxf(a0.x, a0.y), fmaxf(a1.x, a1.y)),
                        fmaxf(fmaxf(a2.x, a2.y), fmaxf(a3.x, a3.y)));
        #pragma unroll
        for (int o = 8; o > 0; o >>= 1)
            m = fmaxf(m, __shfl_xor_sync(0xffffffffu, m, o));
        if ((tid & 15) == 0)
            g_tilemax[(qbase + 4 * qg + i) * 16 + blockIdx.x] = m;
    }
}

// ---------------------------------------------------------------------------
// K3: softmax over k + out[d][q] = sum_m prob[q][m] * value[d][m]
// Block = 8 q rows x ALL 64 d, 256 threads, grid 128 (one wave).
// rowmax comes from g_tilemax (16 values per row, no full-row pass).
// p is UNNORMALIZED exp(s - max); expsum accumulated during p-staging;
// normalization applied once in the epilogue.
// ---------------------------------------------------------------------------
__global__ __launch_bounds__(256)
void k3_softmax_pv(const float* __restrict__ scores,
                   const float* __restrict__ value,
                   float* __restrict__ out)
{
    __shared__ float rowmax[8], rowinv[8];
    __shared__ float p_s[8 * 132];
    __shared__ float red[256 * 32];

    int tid   = threadIdx.x;
    int qbase = blockIdx.x * 8;
    int w     = tid >> 5;
    int lane  = tid & 31;

    // --- rowmax from 16 tile maxima (one warp per q row) ---
    {
        float m = (lane < 16) ? g_tilemax[(qbase + w) * 16 + lane] : -1e30f;
        #pragma unroll
        for (int o = 8; o > 0; o >>= 1)
            m = fmaxf(m, __shfl_xor_sync(0xffffffffu, m, o));
        if (lane == 0) rowmax[w] = m;
    }
    __syncthreads();

    int ms = tid & 15;          // m-slice owner
    int dg = tid >> 4;          // 4 d rows: 4dg..4dg+3
    int m0 = ms * 8;

    ull acc[4][8];              // [d_local][q], packed over m-pairs
    #pragma unroll
    for (int j = 0; j < 4; j++)
        #pragma unroll
        for (int q = 0; q < 8; q++) acc[j][q] = 0ull;

    float psum[4] = {0.0f, 0.0f, 0.0f, 0.0f};   // expsum partials (fixed q per slot)

    // preload scores for chunk 0
    float sr[4];
    #pragma unroll
    for (int it = 0; it < 4; it++) {
        int i = tid + it * 256;
        sr[it] = scores[(qbase + (i >> 7)) * NK + (i & 127)];
    }

    for (int c = 0; c < NK; c += 128) {
        // v: thread-private 4d x 8m straight to registers
        float4 vr[8];
        #pragma unroll
        for (int j = 0; j < 4; j++) {
            const float* vrow = &value[(4 * dg + j) * NK + c + m0];
            vr[j * 2]     = *(const float4*)(vrow);
            vr[j * 2 + 1] = *(const float4*)(vrow + 4);
        }

        __syncthreads();
        // stage unnormalized p (swizzled) + accumulate expsum
        #pragma unroll
        for (int it = 0; it < 4; it++) {
            int i  = tid + it * 256;
            int qq = i >> 7, mm = i & 127;
            int pm = mm ^ (((mm >> 3) & 7) << 2);
            float p = __expf(sr[it] - rowmax[qq]);
            psum[it] += p;
            p_s[qq * 132 + pm] = p;
        }
        __syncthreads();

        // prefetch next chunk's scores
        if (c + 128 < NK) {
            #pragma unroll
            for (int it = 0; it < 4; it++) {
                int i = tid + it * 256;
                sr[it] = scores[(qbase + (i >> 7)) * NK + c + 128 + (i & 127)];
            }
        }

        // compute: 2 quads x 8 q x 4 d, all packed over m
        #pragma unroll
        for (int quad = 0; quad < 2; quad++) {
            int mp = (m0 + quad * 4) ^ ((ms & 7) << 2);
            ull v01[4], v23[4];
            #pragma unroll
            for (int j = 0; j < 4; j++) {
                float4 v4 = vr[j * 2 + quad];
                v01[j] = pk(v4.x, v4.y);
                v23[j] = pk(v4.z, v4.w);
            }
            #pragma unroll
            for (int q = 0; q < 8; q++) {
                ulonglong2 p2 = *(const ulonglong2*)&p_s[q * 132 + mp];
                #pragma unroll
                for (int j = 0; j < 4; j++) {
                    fma2(acc[j][q], p2.x, v01[j]);
                    fma2(acc[j][q], p2.y, v23[j]);
                }
            }
        }
    }

    // --- reduce expsum partials -> rowinv (reuse p_s) ---
    __syncthreads();
    #pragma unroll
    for (int it = 0; it < 4; it++) p_s[tid * 4 + it] = psum[it];
    __syncthreads();
    {
        // warp w reduces q = w: entries p_s[t*4 + (w>>1)] for t in [(w&1)*128, +128)
        int tq = (w & 1) * 128;
        int slot = w >> 1;
        float s = 0.0f;
        #pragma unroll
        for (int j = 0; j < 4; j++)
            s += p_s[(tq + lane + j * 32) * 4 + slot];
        #pragma unroll
        for (int o = 16; o > 0; o >>= 1)
            s += __shfl_xor_sync(0xffffffffu, s, o);
        if (lane == 0) rowinv[w] = 1.0f / s;
    }

    // --- epilogue: horizontal m-pair sum, 16-way ms reduce, normalize ---
    __syncthreads();
    #pragma unroll
    for (int j = 0; j < 4; j++) {
        float s[8];
        #pragma unroll
        for (int q = 0; q < 8; q++) {
            float2 f = upk(acc[j][q]);
            s[q] = f.x + f.y;
        }
        *(float4*)&red[tid * 32 + j * 8]     = make_float4(s[0], s[1], s[2], s[3]);
        *(float4*)&red[tid * 32 + j * 8 + 4] = make_float4(s[4], s[5], s[6], s[7]);
    }
    __syncthreads();

    #pragma unroll
    for (int r = 0; r < 2; r++) {
        int o   = tid + r * 256;      // 512 outputs: 64d x 8q
        int d   = o >> 3, q = o & 7;
        int dgr = d >> 2, dl = d & 3;
        float s0 = 0.0f, s1 = 0.0f, s2 = 0.0f, s3 = 0.0f;
        #pragma unroll
        for (int m = 0; m < 16; m += 4) {
            s0 += red[(dgr * 16 + m)     * 32 + dl * 8 + q];
            s1 += red[(dgr * 16 + m + 1) * 32 + dl * 8 + q];
            s2 += red[(dgr * 16 + m + 2) * 32 + dl * 8 + q];
            s3 += red[(dgr * 16 + m + 3) * 32 + dl * 8 + q];
        }
        out[d * NQ + qbase + q] = rowinv[q] * ((s0 + s1) + (s2 + s3));
    }
}

// ---------------------------------------------------------------------------
// Launch: out = d_out[0 : 64*1024], scores = d_out[64*1024 : +1024*2048]
// ---------------------------------------------------------------------------
extern "C" void kernel_launch(void* const* d_in, const int* in_sizes, int n_in,
                              void* d_out, int out_size)
{
    const float* query = (const float*)d_in[0];
    const float* key   = (const float*)d_in[1];
    const float* value = (const float*)d_in[2];
    const float* W1    = (const float*)d_in[3];
    const float* b1    = (const float*)d_in[4];
    const float* W2    = (const float*)d_in[5];
    const float* b2    = (const float*)d_in[6];

    float* out    = (float*)d_out;
    float* scores = out + D * NQ;

    k1_project<<<dim3((NQ + NK) / 32, 4), 256>>>(query, key, W1, b1);
    k2_scores<<<dim3(NK / 128, NQ / 64), 256>>>(W2, b2, scores);
    k3_softmax_pv<<<NQ / 8, 256>>>(scores, value, out);
}